// round 1
// baseline (speedup 1.0000x reference)
#include <cuda_runtime.h>

// ---------------------------------------------------------------------------
// GIN encoder: 3 x (GINConv(sum-agg) -> MLP(64,relu,64) -> relu -> BN) -> add-pool
// Strategy:
//   * CSR built per call (amortized over 3 layers): hist -> scan -> fill
//   * aggregation: 1 warp / node, float2 / lane, no float atomics
//   * fused MLP kernel: 64-node tile, smem GEMM (fp32 FFMA), relu, BN-stat
//     accumulation (sum, sumsq) in the same kernel
//   * BN folded into the NEXT layer's aggregation as per-feature affine:
//     sum over (self + nbrs) of (a*r+b) = a*(r_self + sum r_nbr) + (deg+1)*b
//   * pool: sorted-batch run-length accumulation, few atomics
// ---------------------------------------------------------------------------

#define MAXN 131072
#define MAXE 2200000

__device__ int   g_deg[MAXN];
__device__ int   g_cursor[MAXN];
__device__ int   g_rowptr[MAXN + 1];
__device__ int   g_col[MAXE];
__device__ int   g_bsum[1024];
__device__ float g_agg[(size_t)MAXN * 64];
__device__ float g_rA[(size_t)MAXN * 64];
__device__ float g_rB[(size_t)MAXN * 64];
__device__ float g_stats[3 * 128];   // per layer: [0:64) sum, [64:128) sumsq
__device__ float g_coef[3 * 128];    // per layer: [0:64) scale a, [64:128) shift b

// ---------------------------- CSR build -----------------------------------

__global__ void k_hist(const int* __restrict__ dst, int E) {
    int e = blockIdx.x * blockDim.x + threadIdx.x;
    if (e < E) atomicAdd(&g_deg[dst[e]], 1);
}

// exclusive scan, stage 1: per-1024-block scan into rowptr + block sums
__global__ void k_scan1(int N) {
    __shared__ int wsum[32];
    int t    = threadIdx.x;            // 1024 threads
    int idx  = blockIdx.x * 1024 + t;
    int v    = (idx < N) ? g_deg[idx] : 0;
    int lane = t & 31, w = t >> 5;
    int inc  = v;
#pragma unroll
    for (int o = 1; o < 32; o <<= 1) {
        int nn = __shfl_up_sync(0xffffffffu, inc, o);
        if (lane >= o) inc += nn;
    }
    if (lane == 31) wsum[w] = inc;
    __syncthreads();
    if (w == 0) {
        int s = wsum[lane];
#pragma unroll
        for (int o = 1; o < 32; o <<= 1) {
            int nn = __shfl_up_sync(0xffffffffu, s, o);
            if (lane >= o) s += nn;
        }
        wsum[lane] = s;  // inclusive scan of warp sums
    }
    __syncthreads();
    int excl = inc - v + (w > 0 ? wsum[w - 1] : 0);
    if (idx < N) g_rowptr[idx] = excl;
    if (t == 0) g_bsum[blockIdx.x] = wsum[31];  // block total
}

// stage 2: exclusive scan of block sums (single block; B <= 128 here)
__global__ void k_scan2(int B) {
    __shared__ int wsum[32];
    int t    = threadIdx.x;  // 1024
    int v    = (t < B) ? g_bsum[t] : 0;
    int lane = t & 31, w = t >> 5;
    int inc  = v;
#pragma unroll
    for (int o = 1; o < 32; o <<= 1) {
        int nn = __shfl_up_sync(0xffffffffu, inc, o);
        if (lane >= o) inc += nn;
    }
    if (lane == 31) wsum[w] = inc;
    __syncthreads();
    if (w == 0) {
        int s = wsum[lane];
#pragma unroll
        for (int o = 1; o < 32; o <<= 1) {
            int nn = __shfl_up_sync(0xffffffffu, s, o);
            if (lane >= o) s += nn;
        }
        wsum[lane] = s;
    }
    __syncthreads();
    int excl = inc - v + (w > 0 ? wsum[w - 1] : 0);
    if (t < B) g_bsum[t] = excl;
}

// stage 3: add block offsets; set rowptr[N] = E
__global__ void k_scan3(int N, int E) {
    int idx = blockIdx.x * blockDim.x + threadIdx.x;
    if (idx < N)       g_rowptr[idx] += g_bsum[idx >> 10];
    else if (idx == N) g_rowptr[N] = E;
}

__global__ void k_fill(const int* __restrict__ src, const int* __restrict__ dst, int E) {
    int e = blockIdx.x * blockDim.x + threadIdx.x;
    if (e < E) {
        int d = dst[e];
        int p = atomicAdd(&g_cursor[d], 1);
        g_col[g_rowptr[d] + p] = src[e];
    }
}

// ---------------------------- aggregation ---------------------------------
// One warp per node. insel: 0 = external x, 1 = g_rA, 2 = g_rB.
// layer > 0: apply previous layer's BN affine on the fly.
__global__ void k_agg(const float* __restrict__ x, int insel, int layer, int N) {
    int gt   = blockIdx.x * blockDim.x + threadIdx.x;
    int node = gt >> 5;
    int lane = gt & 31;
    if (node >= N) return;

    const float* in = (insel == 0) ? x : (insel == 1 ? g_rA : g_rB);
    const float2* inp = (const float2*)in;

    int c   = node * 32 + lane;
    float2 acc = inp[c];  // self term
    int beg = g_rowptr[node], end = g_rowptr[node + 1];

    int e = beg;
    for (; e + 1 < end; e += 2) {
        int s0 = g_col[e], s1 = g_col[e + 1];
        float2 v0 = inp[s0 * 32 + lane];
        float2 v1 = inp[s1 * 32 + lane];
        acc.x += v0.x + v1.x;
        acc.y += v0.y + v1.y;
    }
    if (e < end) {
        float2 v = inp[g_col[e] * 32 + lane];
        acc.x += v.x;
        acc.y += v.y;
    }

    if (layer > 0) {
        const float* cf = &g_coef[(layer - 1) * 128];
        float a0 = cf[2 * lane],      a1 = cf[2 * lane + 1];
        float b0 = cf[64 + 2 * lane], b1 = cf[65 + 2 * lane];
        float cnt = (float)(end - beg + 1);
        acc.x = a0 * acc.x + cnt * b0;
        acc.y = a1 * acc.y + cnt * b1;
    }
    ((float2*)g_agg)[c] = acc;
}

// ---------------------------- fused MLP + relu + BN stats -----------------
// 64-node tile per block, 256 threads, each thread computes a 4x4 fragment
// (m = ty + 16j, n = tx + 16i). A held transposed in smem (As[k][m]).
__global__ __launch_bounds__(256) void k_mlp(
    const float* __restrict__ wa, const float* __restrict__ ba,
    const float* __restrict__ wb, const float* __restrict__ bb,
    int outsel /*1=g_rA, 2=g_rB*/, int layer, int N)
{
    __shared__ float As[64 * 65];
    __shared__ float Ws[64 * 64];
    __shared__ float B1[64], B2[64];
    __shared__ float ssum[64], ssq[64];

    float* r = (outsel == 1) ? g_rA : g_rB;
    int t  = threadIdx.x;
    int m0 = blockIdx.x * 64;

    // load W1 + biases + init stats
#pragma unroll
    for (int i = 0; i < 16; i++) Ws[t + 256 * i] = wa[t + 256 * i];
    if (t < 64) { B1[t] = ba[t]; B2[t] = bb[t]; ssum[t] = 0.f; ssq[t] = 0.f; }

    // load agg tile, transposed
#pragma unroll
    for (int i = 0; i < 4; i++) {
        int f4  = t + 256 * i;        // 0..1023 float4 slots
        int row = f4 >> 4;            // 0..63
        int c4  = (f4 & 15) * 4;      // 0,4,...,60
        float4 v = make_float4(0.f, 0.f, 0.f, 0.f);
        int gm = m0 + row;
        if (gm < N) v = *(const float4*)(g_agg + (size_t)gm * 64 + c4);
        As[(c4 + 0) * 65 + row] = v.x;
        As[(c4 + 1) * 65 + row] = v.y;
        As[(c4 + 2) * 65 + row] = v.z;
        As[(c4 + 3) * 65 + row] = v.w;
    }
    __syncthreads();

    int tx = t & 15, ty = t >> 4;
    float acc[4][4];
#pragma unroll
    for (int j = 0; j < 4; j++)
#pragma unroll
        for (int i = 0; i < 4; i++) acc[j][i] = 0.f;

    // GEMM1: t = relu(A @ W1 + b1)
#pragma unroll
    for (int k = 0; k < 64; k++) {
        float a[4], b[4];
#pragma unroll
        for (int j = 0; j < 4; j++) a[j] = As[k * 65 + ty + 16 * j];
#pragma unroll
        for (int i = 0; i < 4; i++) b[i] = Ws[k * 64 + tx + 16 * i];
#pragma unroll
        for (int j = 0; j < 4; j++)
#pragma unroll
            for (int i = 0; i < 4; i++) acc[j][i] += a[j] * b[i];
    }
    __syncthreads();  // As/Ws free to reuse

    // store intermediate (transposed) into As, load W2 into Ws
    {
        float tv[4][4];
#pragma unroll
        for (int i = 0; i < 4; i++) {
            float bias = B1[tx + 16 * i];
#pragma unroll
            for (int j = 0; j < 4; j++)
                tv[j][i] = fmaxf(acc[j][i] + bias, 0.f);
        }
#pragma unroll
        for (int i = 0; i < 4; i++)
#pragma unroll
            for (int j = 0; j < 4; j++)
                As[(tx + 16 * i) * 65 + ty + 16 * j] = tv[j][i];
    }
#pragma unroll
    for (int i = 0; i < 16; i++) Ws[t + 256 * i] = wb[t + 256 * i];
    __syncthreads();

#pragma unroll
    for (int j = 0; j < 4; j++)
#pragma unroll
        for (int i = 0; i < 4; i++) acc[j][i] = 0.f;

    // GEMM2: o = T @ W2 + b2
#pragma unroll
    for (int k = 0; k < 64; k++) {
        float a[4], b[4];
#pragma unroll
        for (int j = 0; j < 4; j++) a[j] = As[k * 65 + ty + 16 * j];
#pragma unroll
        for (int i = 0; i < 4; i++) b[i] = Ws[k * 64 + tx + 16 * i];
#pragma unroll
        for (int j = 0; j < 4; j++)
#pragma unroll
            for (int i = 0; i < 4; i++) acc[j][i] += a[j] * b[i];
    }

    // epilogue: outer relu, store, accumulate BN stats
#pragma unroll
    for (int i = 0; i < 4; i++) {
        int n = tx + 16 * i;
        float bias = B2[n];
        float s = 0.f, q = 0.f;
#pragma unroll
        for (int j = 0; j < 4; j++) {
            int gm = m0 + ty + 16 * j;
            float v = fmaxf(acc[j][i] + bias, 0.f);
            if (gm < N) {
                r[(size_t)gm * 64 + n] = v;
                s += v;
                q += v * v;
            }
        }
        atomicAdd(&ssum[n], s);
        atomicAdd(&ssq[n], q);
    }
    __syncthreads();
    if (t < 64) {
        atomicAdd(&g_stats[layer * 128 + t],      ssum[t]);
        atomicAdd(&g_stats[layer * 128 + 64 + t], ssq[t]);
    }
}

// ---------------------------- BN finalize ---------------------------------
__global__ void k_bnfin(const float* __restrict__ gamma,
                        const float* __restrict__ beta, int layer, int N) {
    int t = threadIdx.x;  // 64
    if (t >= 64) return;
    float invN = 1.f / (float)N;
    float mean = g_stats[layer * 128 + t] * invN;
    float var  = g_stats[layer * 128 + 64 + t] * invN - mean * mean;
    var = fmaxf(var, 0.f);
    float s = gamma[t] * rsqrtf(var + 1e-5f);
    g_coef[layer * 128 + t]      = s;
    g_coef[layer * 128 + 64 + t] = beta[t] - mean * s;
}

// ---------------------------- pool -----------------------------------------
// batch is sorted: run-length accumulate, atomicAdd only at graph boundaries.
__global__ void k_pool(int insel /*1=g_rA, 2=g_rB*/, const int* __restrict__ batch,
                       float* __restrict__ out, int N) {
    const float* r = (insel == 1) ? g_rA : g_rB;
    const float* cf = &g_coef[2 * 128];
    int t   = threadIdx.x;  // 256
    int f   = t & 63;
    int sub = t >> 6;       // 0..3
    float a = cf[f], b = cf[64 + f];
    int n0  = blockIdx.x * 128;
    int nend = min(n0 + 128, N);
    float acc = 0.f;
    int curg = -1;
    for (int n = n0 + sub; n < nend; n += 4) {
        int g = batch[n];
        if (g != curg) {
            if (curg >= 0) atomicAdd(&out[curg * 64 + f], acc);
            curg = g;
            acc = 0.f;
        }
        acc += a * r[(size_t)n * 64 + f] + b;
    }
    if (curg >= 0) atomicAdd(&out[curg * 64 + f], acc);
}

// ---------------------------- launch ---------------------------------------
extern "C" void kernel_launch(void* const* d_in, const int* in_sizes, int n_in,
                              void* d_out, int out_size) {
    const float* x     = (const float*)d_in[0];
    const int*   ei    = (const int*)d_in[1];
    const int*   batch = (const int*)d_in[2];

    const float* WA[3] = {(const float*)d_in[3],  (const float*)d_in[9],  (const float*)d_in[15]};
    const float* BA[3] = {(const float*)d_in[4],  (const float*)d_in[10], (const float*)d_in[16]};
    const float* WB[3] = {(const float*)d_in[5],  (const float*)d_in[11], (const float*)d_in[17]};
    const float* BB[3] = {(const float*)d_in[6],  (const float*)d_in[12], (const float*)d_in[18]};
    const float* GM[3] = {(const float*)d_in[7],  (const float*)d_in[13], (const float*)d_in[19]};
    const float* BE[3] = {(const float*)d_in[8],  (const float*)d_in[14], (const float*)d_in[20]};

    int N = in_sizes[0] / 64;
    int E = in_sizes[1] / 2;
    const int* src = ei;
    const int* dst = ei + E;

    void *p_deg, *p_cur, *p_stats;
    cudaGetSymbolAddress(&p_deg,   g_deg);
    cudaGetSymbolAddress(&p_cur,   g_cursor);
    cudaGetSymbolAddress(&p_stats, g_stats);

    cudaMemsetAsync(p_deg,   0, (size_t)N * sizeof(int));
    cudaMemsetAsync(p_cur,   0, (size_t)N * sizeof(int));
    cudaMemsetAsync(p_stats, 0, 3 * 128 * sizeof(float));

    // CSR build
    k_hist<<<(E + 255) / 256, 256>>>(dst, E);
    int sb = (N + 1023) / 1024;
    k_scan1<<<sb, 1024>>>(N);
    k_scan2<<<1, 1024>>>(sb);
    k_scan3<<<(N + 1 + 255) / 256, 256>>>(N, E);
    k_fill<<<(E + 255) / 256, 256>>>(src, dst, E);

    // 3 GIN layers; ping-pong rA/rB, BN folded into next aggregation
    int insel = 0;  // x
    for (int L = 0; L < 3; L++) {
        int outsel = (L & 1) ? 2 : 1;  // L0->rA, L1->rB, L2->rA
        k_agg<<<((size_t)N * 32 + 255) / 256, 256>>>(x, insel, L, N);
        k_mlp<<<(N + 63) / 64, 256>>>(WA[L], BA[L], WB[L], BB[L], outsel, L, N);
        k_bnfin<<<1, 64>>>(GM[L], BE[L], L, N);
        insel = outsel;
    }

    cudaMemsetAsync(d_out, 0, (size_t)out_size * sizeof(float));
    k_pool<<<(N + 127) / 128, 256>>>(insel, batch, (float*)d_out, N);
}

// round 2
// speedup vs baseline: 1.0116x; 1.0116x over previous
#include <cuda_runtime.h>

// ---------------------------------------------------------------------------
// GIN encoder: 3 x (GINConv(sum-agg) -> MLP(64,relu,64) -> relu -> BN) -> add-pool
// Round 2: fuse gather + MLP into one kernel so the L2-bound gather phase and
// the FFMA-bound GEMM phase overlap across concurrent blocks on each SM.
//   * CSR built per call (hist -> scan -> fill)
//   * fused kernel: 64-node tile / block (256 thr). Phase A: 8 warps gather
//     8 nodes each (float2/lane, CSR, BN-affine of prev layer folded in),
//     write transposed into smem. Phase B: two 64x64 smem GEMMs (4x4 frags),
//     relu, BN-stat accumulation.
//   * BN folded into the NEXT layer's gather: sum(a*r+b) = a*sum(r)+(deg+1)*b
//   * pool: sorted-batch run-length accumulation
// ---------------------------------------------------------------------------

#define MAXN 131072
#define MAXE 2200000

__device__ int   g_deg[MAXN];
__device__ int   g_cursor[MAXN];
__device__ int   g_rowptr[MAXN + 1];
__device__ int   g_col[MAXE];
__device__ int   g_bsum[1024];
__device__ float g_rA[(size_t)MAXN * 64];
__device__ float g_rB[(size_t)MAXN * 64];
__device__ float g_stats[3 * 128];   // per layer: [0:64) sum, [64:128) sumsq
__device__ float g_coef[3 * 128];    // per layer: [0:64) scale a, [64:128) shift b

// ---------------------------- CSR build -----------------------------------

__global__ void k_hist(const int* __restrict__ dst, int E) {
    int e = blockIdx.x * blockDim.x + threadIdx.x;
    if (e < E) atomicAdd(&g_deg[dst[e]], 1);
}

__global__ void k_scan1(int N) {
    __shared__ int wsum[32];
    int t    = threadIdx.x;            // 1024 threads
    int idx  = blockIdx.x * 1024 + t;
    int v    = (idx < N) ? g_deg[idx] : 0;
    int lane = t & 31, w = t >> 5;
    int inc  = v;
#pragma unroll
    for (int o = 1; o < 32; o <<= 1) {
        int nn = __shfl_up_sync(0xffffffffu, inc, o);
        if (lane >= o) inc += nn;
    }
    if (lane == 31) wsum[w] = inc;
    __syncthreads();
    if (w == 0) {
        int s = wsum[lane];
#pragma unroll
        for (int o = 1; o < 32; o <<= 1) {
            int nn = __shfl_up_sync(0xffffffffu, s, o);
            if (lane >= o) s += nn;
        }
        wsum[lane] = s;
    }
    __syncthreads();
    int excl = inc - v + (w > 0 ? wsum[w - 1] : 0);
    if (idx < N) g_rowptr[idx] = excl;
    if (t == 0) g_bsum[blockIdx.x] = wsum[31];
}

__global__ void k_scan2(int B) {
    __shared__ int wsum[32];
    int t    = threadIdx.x;  // 1024
    int v    = (t < B) ? g_bsum[t] : 0;
    int lane = t & 31, w = t >> 5;
    int inc  = v;
#pragma unroll
    for (int o = 1; o < 32; o <<= 1) {
        int nn = __shfl_up_sync(0xffffffffu, inc, o);
        if (lane >= o) inc += nn;
    }
    if (lane == 31) wsum[w] = inc;
    __syncthreads();
    if (w == 0) {
        int s = wsum[lane];
#pragma unroll
        for (int o = 1; o < 32; o <<= 1) {
            int nn = __shfl_up_sync(0xffffffffu, s, o);
            if (lane >= o) s += nn;
        }
        wsum[lane] = s;
    }
    __syncthreads();
    int excl = inc - v + (w > 0 ? wsum[w - 1] : 0);
    if (t < B) g_bsum[t] = excl;
}

__global__ void k_scan3(int N, int E) {
    int idx = blockIdx.x * blockDim.x + threadIdx.x;
    if (idx < N)       g_rowptr[idx] += g_bsum[idx >> 10];
    else if (idx == N) g_rowptr[N] = E;
}

__global__ void k_fill(const int* __restrict__ src, const int* __restrict__ dst, int E) {
    int e = blockIdx.x * blockDim.x + threadIdx.x;
    if (e < E) {
        int d = dst[e];
        int p = atomicAdd(&g_cursor[d], 1);
        g_col[g_rowptr[d] + p] = src[e];
    }
}

// ---------------------------- fused gather + MLP + relu + BN stats --------
// 64-node tile per block, 256 threads.
// Phase A: warp w gathers nodes [m0+8w, m0+8w+8): self + CSR neighbor sum,
//          float2 per lane, previous layer's BN affine applied on the fly,
//          result written transposed into As[k][m].
// Phase B: GEMM1 (relu) -> GEMM2 -> relu -> store + BN stats.
__global__ __launch_bounds__(256) void k_fused(
    const float* __restrict__ x, int insel /*0=x,1=rA,2=rB*/, int layer,
    const float* __restrict__ wa, const float* __restrict__ ba,
    const float* __restrict__ wb, const float* __restrict__ bb,
    int outsel /*1=g_rA, 2=g_rB*/, int N)
{
    __shared__ float As[64 * 65];
    __shared__ float Ws[64 * 64];
    __shared__ float B1[64], B2[64];
    __shared__ float ssum[64], ssq[64];

    float* r = (outsel == 1) ? g_rA : g_rB;
    int t    = threadIdx.x;
    int warp = t >> 5;
    int lane = t & 31;
    int m0   = blockIdx.x * 64;

    // load W1 + biases + init stats (independent of gather)
#pragma unroll
    for (int i = 0; i < 16; i++) Ws[t + 256 * i] = wa[t + 256 * i];
    if (t < 64) { B1[t] = ba[t]; B2[t] = bb[t]; ssum[t] = 0.f; ssq[t] = 0.f; }

    // ---- Phase A: gather ----
    const float* in = (insel == 0) ? x : (insel == 1 ? g_rA : g_rB);
    const float2* inp = (const float2*)in;

    float a0 = 1.f, a1 = 1.f, b0 = 0.f, b1 = 0.f;
    if (layer > 0) {
        const float* cf = &g_coef[(layer - 1) * 128];
        a0 = cf[2 * lane];      a1 = cf[2 * lane + 1];
        b0 = cf[64 + 2 * lane]; b1 = cf[65 + 2 * lane];
    }

#pragma unroll 1
    for (int i = 0; i < 8; i++) {
        int row  = warp * 8 + i;
        int node = m0 + row;
        float2 acc = make_float2(0.f, 0.f);
        if (node < N) {
            acc = inp[node * 32 + lane];  // self term
            int beg = g_rowptr[node], end = g_rowptr[node + 1];
            int e = beg;
            for (; e + 3 < end; e += 4) {
                int s0 = g_col[e], s1 = g_col[e + 1];
                int s2 = g_col[e + 2], s3 = g_col[e + 3];
                float2 v0 = inp[s0 * 32 + lane];
                float2 v1 = inp[s1 * 32 + lane];
                float2 v2 = inp[s2 * 32 + lane];
                float2 v3 = inp[s3 * 32 + lane];
                acc.x += (v0.x + v1.x) + (v2.x + v3.x);
                acc.y += (v0.y + v1.y) + (v2.y + v3.y);
            }
            for (; e < end; e++) {
                float2 v = inp[g_col[e] * 32 + lane];
                acc.x += v.x;
                acc.y += v.y;
            }
            if (layer > 0) {
                float cnt = (float)(end - beg + 1);
                acc.x = a0 * acc.x + cnt * b0;
                acc.y = a1 * acc.y + cnt * b1;
            }
        }
        As[(2 * lane) * 65 + row]     = acc.x;
        As[(2 * lane + 1) * 65 + row] = acc.y;
    }
    __syncthreads();

    // ---- Phase B: GEMMs ----
    int tx = t & 15, ty = t >> 4;
    float acc[4][4];
#pragma unroll
    for (int j = 0; j < 4; j++)
#pragma unroll
        for (int i = 0; i < 4; i++) acc[j][i] = 0.f;

    // GEMM1: h = relu(A @ W1 + b1)
#pragma unroll
    for (int k = 0; k < 64; k++) {
        float a[4], b[4];
#pragma unroll
        for (int j = 0; j < 4; j++) a[j] = As[k * 65 + ty + 16 * j];
#pragma unroll
        for (int i = 0; i < 4; i++) b[i] = Ws[k * 64 + tx + 16 * i];
#pragma unroll
        for (int j = 0; j < 4; j++)
#pragma unroll
            for (int i = 0; i < 4; i++) acc[j][i] += a[j] * b[i];
    }
    __syncthreads();

    // store intermediate (transposed) into As, load W2 into Ws
    {
        float tv[4][4];
#pragma unroll
        for (int i = 0; i < 4; i++) {
            float bias = B1[tx + 16 * i];
#pragma unroll
            for (int j = 0; j < 4; j++)
                tv[j][i] = fmaxf(acc[j][i] + bias, 0.f);
        }
#pragma unroll
        for (int i = 0; i < 4; i++)
#pragma unroll
            for (int j = 0; j < 4; j++)
                As[(tx + 16 * i) * 65 + ty + 16 * j] = tv[j][i];
    }
#pragma unroll
    for (int i = 0; i < 16; i++) Ws[t + 256 * i] = wb[t + 256 * i];
    __syncthreads();

#pragma unroll
    for (int j = 0; j < 4; j++)
#pragma unroll
        for (int i = 0; i < 4; i++) acc[j][i] = 0.f;

    // GEMM2: o = h @ W2 + b2
#pragma unroll
    for (int k = 0; k < 64; k++) {
        float a[4], b[4];
#pragma unroll
        for (int j = 0; j < 4; j++) a[j] = As[k * 65 + ty + 16 * j];
#pragma unroll
        for (int i = 0; i < 4; i++) b[i] = Ws[k * 64 + tx + 16 * i];
#pragma unroll
        for (int j = 0; j < 4; j++)
#pragma unroll
            for (int i = 0; i < 4; i++) acc[j][i] += a[j] * b[i];
    }

    // epilogue: outer relu, store, BN stats
#pragma unroll
    for (int i = 0; i < 4; i++) {
        int n = tx + 16 * i;
        float bias = B2[n];
        float s = 0.f, q = 0.f;
#pragma unroll
        for (int j = 0; j < 4; j++) {
            int gm = m0 + ty + 16 * j;
            float v = fmaxf(acc[j][i] + bias, 0.f);
            if (gm < N) {
                r[(size_t)gm * 64 + n] = v;
                s += v;
                q += v * v;
            }
        }
        atomicAdd(&ssum[n], s);
        atomicAdd(&ssq[n], q);
    }
    __syncthreads();
    if (t < 64) {
        atomicAdd(&g_stats[layer * 128 + t],      ssum[t]);
        atomicAdd(&g_stats[layer * 128 + 64 + t], ssq[t]);
    }
}

// ---------------------------- BN finalize ---------------------------------
__global__ void k_bnfin(const float* __restrict__ gamma,
                        const float* __restrict__ beta, int layer, int N) {
    int t = threadIdx.x;  // 64
    if (t >= 64) return;
    float invN = 1.f / (float)N;
    float mean = g_stats[layer * 128 + t] * invN;
    float var  = g_stats[layer * 128 + 64 + t] * invN - mean * mean;
    var = fmaxf(var, 0.f);
    float s = gamma[t] * rsqrtf(var + 1e-5f);
    g_coef[layer * 128 + t]      = s;
    g_coef[layer * 128 + 64 + t] = beta[t] - mean * s;
}

// ---------------------------- pool -----------------------------------------
__global__ void k_pool(int insel /*1=g_rA, 2=g_rB*/, const int* __restrict__ batch,
                       float* __restrict__ out, int N) {
    const float* r = (insel == 1) ? g_rA : g_rB;
    const float* cf = &g_coef[2 * 128];
    int t   = threadIdx.x;  // 256
    int f   = t & 63;
    int sub = t >> 6;       // 0..3
    float a = cf[f], b = cf[64 + f];
    int n0  = blockIdx.x * 128;
    int nend = min(n0 + 128, N);
    float acc = 0.f;
    int curg = -1;
    for (int n = n0 + sub; n < nend; n += 4) {
        int g = batch[n];
        if (g != curg) {
            if (curg >= 0) atomicAdd(&out[curg * 64 + f], acc);
            curg = g;
            acc = 0.f;
        }
        acc += a * r[(size_t)n * 64 + f] + b;
    }
    if (curg >= 0) atomicAdd(&out[curg * 64 + f], acc);
}

// ---------------------------- launch ---------------------------------------
extern "C" void kernel_launch(void* const* d_in, const int* in_sizes, int n_in,
                              void* d_out, int out_size) {
    const float* x     = (const float*)d_in[0];
    const int*   ei    = (const int*)d_in[1];
    const int*   batch = (const int*)d_in[2];

    const float* WA[3] = {(const float*)d_in[3],  (const float*)d_in[9],  (const float*)d_in[15]};
    const float* BA[3] = {(const float*)d_in[4],  (const float*)d_in[10], (const float*)d_in[16]};
    const float* WB[3] = {(const float*)d_in[5],  (const float*)d_in[11], (const float*)d_in[17]};
    const float* BB[3] = {(const float*)d_in[6],  (const float*)d_in[12], (const float*)d_in[18]};
    const float* GM[3] = {(const float*)d_in[7],  (const float*)d_in[13], (const float*)d_in[19]};
    const float* BE[3] = {(const float*)d_in[8],  (const float*)d_in[14], (const float*)d_in[20]};

    int N = in_sizes[0] / 64;
    int E = in_sizes[1] / 2;
    const int* src = ei;
    const int* dst = ei + E;

    void *p_deg, *p_cur, *p_stats;
    cudaGetSymbolAddress(&p_deg,   g_deg);
    cudaGetSymbolAddress(&p_cur,   g_cursor);
    cudaGetSymbolAddress(&p_stats, g_stats);

    cudaMemsetAsync(p_deg,   0, (size_t)N * sizeof(int));
    cudaMemsetAsync(p_cur,   0, (size_t)N * sizeof(int));
    cudaMemsetAsync(p_stats, 0, 3 * 128 * sizeof(float));

    // CSR build
    k_hist<<<(E + 255) / 256, 256>>>(dst, E);
    int sb = (N + 1023) / 1024;
    k_scan1<<<sb, 1024>>>(N);
    k_scan2<<<1, 1024>>>(sb);
    k_scan3<<<(N + 1 + 255) / 256, 256>>>(N, E);
    k_fill<<<(E + 255) / 256, 256>>>(src, dst, E);

    // 3 GIN layers, fused gather+MLP; ping-pong rA/rB
    int insel = 0;  // x
    for (int L = 0; L < 3; L++) {
        int outsel = (L & 1) ? 2 : 1;  // L0->rA, L1->rB, L2->rA
        k_fused<<<(N + 63) / 64, 256>>>(x, insel, L,
                                        WA[L], BA[L], WB[L], BB[L], outsel, N);
        k_bnfin<<<1, 64>>>(GM[L], BE[L], L, N);
        insel = outsel;
    }

    cudaMemsetAsync(d_out, 0, (size_t)out_size * sizeof(float));
    k_pool<<<(N + 127) / 128, 256>>>(insel, batch, (float*)d_out, N);
}